// round 2
// baseline (speedup 1.0000x reference)
#include <cuda_runtime.h>
#include <math.h>

#define EMB    2048
#define RANK   4
#define VOCAB  8192
#define HLEN   4
#define BATCH  256
#define NCOLS  (VOCAB * RANK * RANK)   // 131072
#define EPS    1e-10f

// ---------------- scratch (__device__ globals: no allocation allowed) -------
__device__ float g_partial[BATCH * 1024 * 4];          // 4 MB, deterministic
__device__ float g_sel  [BATCH * HLEN * RANK * RANK];  // selected core entries
__device__ float g_alpha[BATCH * RANK];
__device__ float g_beta [BATCH * RANK];
__device__ int   g_idx32[BATCH * HLEN];                // normalized indices

typedef unsigned long long u64;

__device__ __forceinline__ u64 pack2(float lo, float hi) {
    u64 r; asm("mov.b64 %0, {%1, %2};" : "=l"(r) : "f"(lo), "f"(hi)); return r;
}
__device__ __forceinline__ void fma2(u64 &acc, u64 a, u64 b) {
    asm("fma.rn.f32x2 %0, %1, %2, %0;" : "+l"(acc) : "l"(a), "l"(b));
}
__device__ __forceinline__ float2 unpack2(u64 v) {
    float2 r; asm("mov.b64 {%0, %1}, %2;" : "=f"(r.x), "=f"(r.y) : "l"(v)); return r;
}

// ---------------------------------------------------------------------------
// Kernel 0: normalize indices to int32, auto-detecting int32 vs int64 layout.
// Scans only the first BATCH*HLEN int32 words (4 KB) — safe under both dtypes.
// int64 data (values < VOCAB) has ALL odd words == 0; random int32 data does
// not (P ~ 8192^-512). Single block, deterministic.
// ---------------------------------------------------------------------------
__global__ void normalize_indices(const void* __restrict__ idx_raw) {
    __shared__ int odd_nonzero;
    const int* w32 = (const int*)idx_raw;
    if (threadIdx.x == 0) odd_nonzero = 0;
    __syncthreads();
    for (int p = threadIdx.x; p < BATCH * HLEN; p += blockDim.x)
        if ((p & 1) && w32[p] != 0) atomicOr(&odd_nonzero, 1);
    __syncthreads();
    const bool is64 = (odd_nonzero == 0);
    const long long* w64 = (const long long*)idx_raw;
    for (int p = threadIdx.x; p < BATCH * HLEN; p += blockDim.x)
        g_idx32[p] = is64 ? (int)w64[p] : w32[p];
}

// ---------------------------------------------------------------------------
// Kernel A: D = x @ w_vocab, fused relu + per-(i, j=col&3) column reduction.
// Tile: BM=128, BN=128, BK=16. 256 threads, 8x8 microtile, packed f32x2 FMA.
// grid = (1024, 2). Each 128-col tile lies inside one rank-i slab
// (32768 % 128 == 0); bn chunks of 256 correspond exactly to i = 0..3.
// ---------------------------------------------------------------------------
__global__ __launch_bounds__(256, 2)
void gemm_relu_reduce(const float* __restrict__ x, const float* __restrict__ w) {
    __shared__ float As[16][132];   // x tile, transposed [k][m], padded
    __shared__ float Bs[16][128];   // w tile [k][n]

    const int bn = blockIdx.x;          // 0..1023
    const int bm = blockIdx.y;          // 0..1
    const int t  = threadIdx.x;
    const int tm = t >> 4;              // 0..15
    const int tn = t & 15;              // 0..15

    u64 acc2[8][4];
    #pragma unroll
    for (int ii = 0; ii < 8; ii++)
        #pragma unroll
        for (int p = 0; p < 4; p++) acc2[ii][p] = 0ull;

    const float* xg = x + (size_t)(bm * 128) * EMB;

    for (int k0 = 0; k0 < EMB; k0 += 16) {
        #pragma unroll
        for (int i = 0; i < 2; i++) {
            int id  = t + 256 * i;                 // 0..511
            int row = id >> 2;                     // 0..127
            int c4  = (id & 3) * 4;                // 0,4,8,12
            float4 v = *(const float4*)(xg + (size_t)row * EMB + k0 + c4);
            As[c4 + 0][row] = v.x;
            As[c4 + 1][row] = v.y;
            As[c4 + 2][row] = v.z;
            As[c4 + 3][row] = v.w;
        }
        #pragma unroll
        for (int i = 0; i < 2; i++) {
            int id = t + 256 * i;                  // 0..511
            int kr = id >> 5;                      // 0..15
            int c4 = (id & 31) * 4;                // 0..124
            float4 v = *(const float4*)(w + (size_t)(k0 + kr) * NCOLS
                                          + (size_t)bn * 128 + c4);
            *(float4*)&Bs[kr][c4] = v;
        }
        __syncthreads();

        #pragma unroll
        for (int kk = 0; kk < 16; kk++) {
            float4 a0 = *(const float4*)&As[kk][tm * 8];
            float4 a1 = *(const float4*)&As[kk][tm * 8 + 4];
            const u64* bp = (const u64*)&Bs[kk][tn * 8];
            u64 b2[4];
            b2[0] = bp[0]; b2[1] = bp[1]; b2[2] = bp[2]; b2[3] = bp[3];
            float av[8] = {a0.x, a0.y, a0.z, a0.w, a1.x, a1.y, a1.z, a1.w};
            #pragma unroll
            for (int ii = 0; ii < 8; ii++) {
                u64 aa = pack2(av[ii], av[ii]);
                #pragma unroll
                for (int p = 0; p < 4; p++) fma2(acc2[ii][p], aa, b2[p]);
            }
        }
        __syncthreads();
    }

    // --- epilogue: relu, bucket by (col & 3), reduce over tn (16 lanes) ---
    float s[8][4];
    #pragma unroll
    for (int ii = 0; ii < 8; ii++) {
        s[ii][0] = s[ii][1] = s[ii][2] = s[ii][3] = 0.f;
        #pragma unroll
        for (int p = 0; p < 4; p++) {
            float2 v = unpack2(acc2[ii][p]);
            s[ii][(2 * p)     & 3] += fmaxf(v.x, 0.f);
            s[ii][(2 * p + 1) & 3] += fmaxf(v.y, 0.f);
        }
    }
    #pragma unroll
    for (int off = 8; off > 0; off >>= 1)
        #pragma unroll
        for (int ii = 0; ii < 8; ii++)
            #pragma unroll
            for (int j = 0; j < 4; j++)
                s[ii][j] += __shfl_down_sync(0xffffffffu, s[ii][j], off, 16);

    if (tn == 0) {
        #pragma unroll
        for (int ii = 0; ii < 8; ii++) {
            int row = bm * 128 + tm * 8 + ii;
            float4 v = make_float4(s[ii][0], s[ii][1], s[ii][2], s[ii][3]);
            *(float4*)&g_partial[((size_t)row * 1024 + bn) * 4] = v;
        }
    }
}

// ---------------------------------------------------------------------------
// Kernel B: alpha, beta, and the 64 gathered core entries per batch.
// ---------------------------------------------------------------------------
__global__ __launch_bounds__(256)
void small_dots(const float* __restrict__ x,
                const float* __restrict__ wa,
                const float* __restrict__ wb,
                const float* __restrict__ wv) {
    __shared__ float sx[EMB];
    const int b = blockIdx.x;
    const int t = threadIdx.x;
    for (int k = t; k < EMB; k += 256) sx[k] = x[(size_t)b * EMB + k];
    __syncthreads();

    const int w    = t >> 5;
    const int lane = t & 31;

    for (int task = w; task < 18; task += 8) {
        const float* base;
        size_t stride;
        int h = 0, i = 0;
        if (task < 16) {
            h = task >> 2; i = task & 3;
            int v = g_idx32[b * HLEN + h];
            base   = wv + (size_t)i * (VOCAB * RANK) + (size_t)v * RANK;
            stride = NCOLS;
        } else {
            base   = (task == 16) ? wa : wb;
            stride = RANK;
        }
        float a0 = 0.f, a1 = 0.f, a2 = 0.f, a3 = 0.f;
        for (int k = lane; k < EMB; k += 32) {
            float  xv = sx[k];
            float4 w4 = *(const float4*)(base + (size_t)k * stride);
            a0 += xv * w4.x; a1 += xv * w4.y;
            a2 += xv * w4.z; a3 += xv * w4.w;
        }
        #pragma unroll
        for (int off = 16; off > 0; off >>= 1) {
            a0 += __shfl_down_sync(0xffffffffu, a0, off);
            a1 += __shfl_down_sync(0xffffffffu, a1, off);
            a2 += __shfl_down_sync(0xffffffffu, a2, off);
            a3 += __shfl_down_sync(0xffffffffu, a3, off);
        }
        if (lane == 0) {
            float r0 = fmaxf(a0, 0.f) + EPS;
            float r1 = fmaxf(a1, 0.f) + EPS;
            float r2 = fmaxf(a2, 0.f) + EPS;
            float r3 = fmaxf(a3, 0.f) + EPS;
            if (task < 16) {
                float* d = &g_sel[(((b * HLEN + h) * RANK) + i) * RANK];
                d[0] = r0; d[1] = r1; d[2] = r2; d[3] = r3;
            } else if (task == 16) {
                g_alpha[b * RANK + 0] = r0; g_alpha[b * RANK + 1] = r1;
                g_alpha[b * RANK + 2] = r2; g_alpha[b * RANK + 3] = r3;
            } else {
                g_beta[b * RANK + 0] = r0; g_beta[b * RANK + 1] = r1;
                g_beta[b * RANK + 2] = r2; g_beta[b * RANK + 3] = r3;
            }
        }
    }
}

// ---------------------------------------------------------------------------
// Kernel C: reduce partials -> cm, then the 4x4 chains + nll per batch.
// bn chunk q (0..3) of 256 blocks == rank slab i=q, so v[i][j] -> cm[i][j].
// ---------------------------------------------------------------------------
__global__ __launch_bounds__(256)
void finalize(float* __restrict__ out) {
    const int b = blockIdx.x;
    const int t = threadIdx.x;

    float v[4][4];
    #pragma unroll
    for (int i = 0; i < 4; i++) {
        float4 p = *(const float4*)&g_partial[(((size_t)b * 1024) + i * 256 + t) * 4];
        v[i][0] = p.x; v[i][1] = p.y; v[i][2] = p.z; v[i][3] = p.w;
    }
    #pragma unroll
    for (int off = 16; off > 0; off >>= 1)
        #pragma unroll
        for (int i = 0; i < 4; i++)
            #pragma unroll
            for (int j = 0; j < 4; j++)
                v[i][j] += __shfl_down_sync(0xffffffffu, v[i][j], off);

    __shared__ float ws[8][16];
    const int w = t >> 5, lane = t & 31;
    if (lane == 0) {
        #pragma unroll
        for (int i = 0; i < 4; i++)
            #pragma unroll
            for (int j = 0; j < 4; j++)
                ws[w][i * 4 + j] = v[i][j];
    }
    __syncthreads();

    if (t == 0) {
        float cm[4][4];
        #pragma unroll
        for (int i = 0; i < 4; i++)
            #pragma unroll
            for (int j = 0; j < 4; j++) {
                float s = (float)VOCAB * EPS;   // EPS added per core element
                #pragma unroll
                for (int q = 0; q < 8; q++) s += ws[q][i * 4 + j];
                cm[i][j] = s;
            }

        float al[4], be[4];
        #pragma unroll
        for (int i = 0; i < 4; i++) { al[i] = g_alpha[b * 4 + i]; be[i] = g_beta[b * 4 + i]; }

        float m[4][4], tmp[4][4];
        const float* s0 = &g_sel[(b * HLEN + 0) * 16];
        #pragma unroll
        for (int i = 0; i < 4; i++)
            #pragma unroll
            for (int j = 0; j < 4; j++) m[i][j] = s0[i * 4 + j];
        for (int h = 1; h < HLEN; h++) {
            const float* sh = &g_sel[(b * HLEN + h) * 16];
            #pragma unroll
            for (int i = 0; i < 4; i++)
                #pragma unroll
                for (int j = 0; j < 4; j++) {
                    float acc = 0.f;
                    #pragma unroll
                    for (int k = 0; k < 4; k++) acc += m[i][k] * sh[k * 4 + j];
                    tmp[i][j] = acc;
                }
            #pragma unroll
            for (int i = 0; i < 4; i++)
                #pragma unroll
                for (int j = 0; j < 4; j++) m[i][j] = tmp[i][j];
        }
        float p_tilde = 0.f;
        #pragma unroll
        for (int i = 0; i < 4; i++)
            #pragma unroll
            for (int j = 0; j < 4; j++) p_tilde += al[i] * m[i][j] * be[j];

        float z[4][4];
        #pragma unroll
        for (int i = 0; i < 4; i++)
            #pragma unroll
            for (int j = 0; j < 4; j++) z[i][j] = cm[i][j];
        for (int r = 0; r < HLEN - 1; r++) {
            #pragma unroll
            for (int i = 0; i < 4; i++)
                #pragma unroll
                for (int j = 0; j < 4; j++) {
                    float acc = 0.f;
                    #pragma unroll
                    for (int k = 0; k < 4; k++) acc += z[i][k] * cm[k][j];
                    tmp[i][j] = acc;
                }
            #pragma unroll
            for (int i = 0; i < 4; i++)
                #pragma unroll
                for (int j = 0; j < 4; j++) z[i][j] = tmp[i][j];
        }
        float norm_const = 0.f;
        #pragma unroll
        for (int i = 0; i < 4; i++)
            #pragma unroll
            for (int j = 0; j < 4; j++) norm_const += al[i] * z[i][j] * be[j];

        out[b] = logf(norm_const) - logf(p_tilde);
    }
}

// ---------------------------------------------------------------------------
extern "C" void kernel_launch(void* const* d_in, const int* in_sizes, int n_in,
                              void* d_out, int out_size) {
    // Identify inputs by element count (robust to metadata ordering):
    //   x        : 256*2048      = 524288
    //   w_alpha  : 2048*4        = 8192   (first of the two)
    //   w_beta   : 2048*4        = 8192   (second)
    //   w_vocab  : 2048*131072   = 268435456
    //   indices  : 256*4         = 1024
    const float* x  = nullptr;
    const float* wa = nullptr;
    const float* wb = nullptr;
    const float* wv = nullptr;
    const void*  ix = nullptr;
    for (int i = 0; i < n_in; i++) {
        int s = in_sizes[i];
        if      (s == BATCH * EMB)        x  = (const float*)d_in[i];
        else if (s == 1024 * 262144)      wv = (const float*)d_in[i];  // 268435456
        else if (s == BATCH * HLEN)       ix = d_in[i];
        else if (s == EMB * RANK)         { if (!wa) wa = (const float*)d_in[i];
                                            else     wb = (const float*)d_in[i]; }
    }
    // Fallback to positional order if anything missing
    if (!x || !wa || !wb || !wv || !ix) {
        x  = (const float*)d_in[0];
        wa = (const float*)d_in[1];
        wb = (const float*)d_in[2];
        wv = (const float*)d_in[3];
        ix = d_in[4];
    }
    float* out = (float*)d_out;

    normalize_indices<<<1, 256>>>(ix);
    gemm_relu_reduce<<<dim3(1024, 2), 256>>>(x, wv);
    small_dots<<<BATCH, 256>>>(x, wa, wb, wv);
    finalize<<<BATCH, 256>>>(out);
}

// round 4
// speedup vs baseline: 2.6806x; 2.6806x over previous
#include <cuda_runtime.h>
#include <math.h>
#include <stdint.h>

#define EMB    2048
#define RANK   4
#define VOCAB  8192
#define HLEN   4
#define BATCH  256
#define NCOLS  (VOCAB * RANK * RANK)   // 131072
#define EPS    1e-10f

// ---------------- scratch (__device__ globals) -------------------------------
__device__ float g_partial[BATCH * 1024 * 4];          // [row][tile 1024][j]
__device__ float g_sel  [BATCH * HLEN * RANK * RANK];
__device__ float g_alpha[BATCH * RANK];
__device__ float g_beta [BATCH * RANK];
__device__ int   g_idx32[BATCH * HLEN];

__device__ __forceinline__ uint32_t smem_u32(const void* p) {
    uint32_t a;
    asm("{ .reg .u64 t; cvta.to.shared.u64 t, %1; cvt.u32.u64 %0, t; }"
        : "=r"(a) : "l"(p));
    return a;
}
__device__ __forceinline__ void cp_async16(uint32_t saddr, const void* gaddr) {
    asm volatile("cp.async.cg.shared.global [%0], [%1], 16;"
                 :: "r"(saddr), "l"(gaddr) : "memory");
}
__device__ __forceinline__ void cp_commit() {
    asm volatile("cp.async.commit_group;" ::: "memory");
}
template <int N>
__device__ __forceinline__ void cp_wait() {
    asm volatile("cp.async.wait_group %0;" :: "n"(N) : "memory");
}
__device__ __forceinline__ void mma_tf32(float c[4], const uint32_t a[4],
                                         const uint32_t b[2]) {
    asm volatile(
        "mma.sync.aligned.m16n8k8.row.col.f32.tf32.tf32.f32 "
        "{%0,%1,%2,%3}, {%4,%5,%6,%7}, {%8,%9}, {%0,%1,%2,%3};"
        : "+f"(c[0]), "+f"(c[1]), "+f"(c[2]), "+f"(c[3])
        : "r"(a[0]), "r"(a[1]), "r"(a[2]), "r"(a[3]), "r"(b[0]), "r"(b[1]));
}

// =============================================================================
// HMMA tf32 GEMM: D[128 batch rows][128 W cols] per CTA, fused relu +
// j-bucket (col&3) reduction into g_partial[row][bn][4].
// grid (1024, 2), 256 threads = 8 warps (2 m x 4 n), warp tile 64x32.
// =============================================================================
#define AP 20     // A smem row pitch (floats): conflict-free + 16B aligned
#define BP 132    // B smem row pitch (floats)

__global__ __launch_bounds__(256, 2)
void gemm_mma(const float* __restrict__ x, const float* __restrict__ w) {
    __shared__ float As[2][128 * AP];   // [m][k] 10240 B/stage
    __shared__ float Bs[2][16 * BP];    // [k][n]  8448 B/stage
    __shared__ float red[4][128][4];    // epilogue per-n-warp slices

    const int t    = threadIdx.x;
    const int lane = t & 31;
    const int wid  = t >> 5;
    const int wy   = wid >> 2;          // 0..1  (m group of 64)
    const int wx   = wid & 3;           // 0..3  (n group of 32)
    const int bn   = blockIdx.x;        // 0..1023
    const int bm   = blockIdx.y;        // 0..1
    const int q    = lane & 3;          // thread-in-group
    const int g    = lane >> 2;         // group id (0..7)

    float acc[4][4][4];
    #pragma unroll
    for (int mf = 0; mf < 4; mf++)
        #pragma unroll
        for (int nf = 0; nf < 4; nf++)
            #pragma unroll
            for (int r = 0; r < 4; r++) acc[mf][nf][r] = 0.f;

    const float* xg = x + (size_t)(bm * 128) * EMB;
    const float* wg = w + (size_t)bn * 128;

    // --- stage issue: A = x[128 x 16], B = w[16 x 128] -----------------------
    auto issue = [&](int c, int s) {
        #pragma unroll
        for (int i = 0; i < 2; i++) {
            int id  = t + 256 * i;              // 0..511
            int row = id >> 2;                  // 0..127
            int seg = id & 3;                   // 16B segment
            cp_async16(smem_u32(&As[s][row * AP + seg * 4]),
                       xg + (size_t)row * EMB + c * 16 + seg * 4);
        }
        #pragma unroll
        for (int i = 0; i < 2; i++) {
            int id  = t + 256 * i;
            int kr  = id >> 5;                  // 0..15
            int seg = id & 31;
            cp_async16(smem_u32(&Bs[s][kr * BP + seg * 4]),
                       wg + (size_t)(c * 16 + kr) * NCOLS + seg * 4);
        }
        cp_commit();
    };

    issue(0, 0);
    const int NIT = EMB / 16;   // 128

    for (int c = 0; c < NIT; c++) {
        const int s = c & 1;
        if (c + 1 < NIT) { issue(c + 1, s ^ 1); cp_wait<1>(); }
        else             { cp_wait<0>(); }
        __syncthreads();

        #pragma unroll
        for (int k0 = 0; k0 < 16; k0 += 8) {
            uint32_t a[4][4], b[4][2];
            #pragma unroll
            for (int mf = 0; mf < 4; mf++) {
                int row = wy * 64 + mf * 16 + g;
                a[mf][0] = __float_as_uint(As[s][ row      * AP + k0 + q    ]);
                a[mf][1] = __float_as_uint(As[s][(row + 8) * AP + k0 + q    ]);
                a[mf][2] = __float_as_uint(As[s][ row      * AP + k0 + q + 4]);
                a[mf][3] = __float_as_uint(As[s][(row + 8) * AP + k0 + q + 4]);
            }
            #pragma unroll
            for (int nf = 0; nf < 4; nf++) {
                int n = wx * 32 + nf * 8 + g;
                b[nf][0] = __float_as_uint(Bs[s][(k0 + q)     * BP + n]);
                b[nf][1] = __float_as_uint(Bs[s][(k0 + q + 4) * BP + n]);
            }
            #pragma unroll
            for (int mf = 0; mf < 4; mf++)
                #pragma unroll
                for (int nf = 0; nf < 4; nf++)
                    mma_tf32(acc[mf][nf], a[mf], b[nf]);
        }
        __syncthreads();
    }

    // --- epilogue: relu + j-bucket reduce ------------------------------------
    // C frag: c0/c1 at row g (cols 2q, 2q+1), c2/c3 at row g+8.
    // global n = bn*128 + wx*32 + nf*8 + 2q + reg; j = n&3 = (2q + reg)&3.
    float sj[4][2][2];   // [mf][rowhalf][reg]
    #pragma unroll
    for (int mf = 0; mf < 4; mf++) {
        sj[mf][0][0] = sj[mf][0][1] = sj[mf][1][0] = sj[mf][1][1] = 0.f;
        #pragma unroll
        for (int nf = 0; nf < 4; nf++) {
            sj[mf][0][0] += fmaxf(acc[mf][nf][0], 0.f);
            sj[mf][0][1] += fmaxf(acc[mf][nf][1], 0.f);
            sj[mf][1][0] += fmaxf(acc[mf][nf][2], 0.f);
            sj[mf][1][1] += fmaxf(acc[mf][nf][3], 0.f);
        }
        // lanes (q even) hold j{0,1}; (q odd) hold j{2,3}; xor-2 merges q pairs
        #pragma unroll
        for (int hh = 0; hh < 2; hh++)
            #pragma unroll
            for (int r = 0; r < 2; r++)
                sj[mf][hh][r] += __shfl_xor_sync(0xffffffffu, sj[mf][hh][r], 2);
    }
    if ((q >> 1) == 0) {               // q == 0 or 1 write; q 2,3 are dups
        const int jbase = (q & 1) ? 2 : 0;
        #pragma unroll
        for (int mf = 0; mf < 4; mf++)
            #pragma unroll
            for (int hh = 0; hh < 2; hh++) {
                int m = wy * 64 + mf * 16 + g + 8 * hh;
                red[wx][m][jbase + 0] = sj[mf][hh][0];
                red[wx][m][jbase + 1] = sj[mf][hh][1];
            }
    }
    __syncthreads();
    if (t < 128) {
        float4 v;
        v.x = red[0][t][0] + red[1][t][0] + red[2][t][0] + red[3][t][0];
        v.y = red[0][t][1] + red[1][t][1] + red[2][t][1] + red[3][t][1];
        v.z = red[0][t][2] + red[1][t][2] + red[2][t][2] + red[3][t][2];
        v.w = red[0][t][3] + red[1][t][3] + red[2][t][3] + red[3][t][3];
        int row = bm * 128 + t;
        *(float4*)&g_partial[((size_t)row * 1024 + bn) * 4] = v;
    }
}

// =============================================================================
// indices normalize / small dots / finalize (unchanged, validated in R2)
// =============================================================================
__global__ void normalize_indices(const void* __restrict__ idx_raw) {
    __shared__ int odd_nonzero;
    const int* w32 = (const int*)idx_raw;
    if (threadIdx.x == 0) odd_nonzero = 0;
    __syncthreads();
    for (int p = threadIdx.x; p < BATCH * HLEN; p += blockDim.x)
        if ((p & 1) && w32[p] != 0) atomicOr(&odd_nonzero, 1);
    __syncthreads();
    const bool is64 = (odd_nonzero == 0);
    const long long* w64 = (const long long*)idx_raw;
    for (int p = threadIdx.x; p < BATCH * HLEN; p += blockDim.x)
        g_idx32[p] = is64 ? (int)w64[p] : w32[p];
}

__global__ __launch_bounds__(256)
void small_dots(const float* __restrict__ x, const float* __restrict__ wa,
                const float* __restrict__ wb, const float* __restrict__ wv) {
    __shared__ float sx[EMB];
    const int b = blockIdx.x, t = threadIdx.x;
    for (int k = t; k < EMB; k += 256) sx[k] = x[(size_t)b * EMB + k];
    __syncthreads();
    const int w = t >> 5, lane = t & 31;
    for (int task = w; task < 18; task += 8) {
        const float* base; size_t stride; int h = 0, i = 0;
        if (task < 16) {
            h = task >> 2; i = task & 3;
            int v = g_idx32[b * HLEN + h];
            base = wv + (size_t)i * (VOCAB * RANK) + (size_t)v * RANK;
            stride = NCOLS;
        } else { base = (task == 16) ? wa : wb; stride = RANK; }
        float a0 = 0.f, a1 = 0.f, a2 = 0.f, a3 = 0.f;
        for (int k = lane; k < EMB; k += 32) {
            float xv = sx[k];
            float4 w4 = *(const float4*)(base + (size_t)k * stride);
            a0 += xv * w4.x; a1 += xv * w4.y; a2 += xv * w4.z; a3 += xv * w4.w;
        }
        #pragma unroll
        for (int off = 16; off > 0; off >>= 1) {
            a0 += __shfl_down_sync(0xffffffffu, a0, off);
            a1 += __shfl_down_sync(0xffffffffu, a1, off);
            a2 += __shfl_down_sync(0xffffffffu, a2, off);
            a3 += __shfl_down_sync(0xffffffffu, a3, off);
        }
        if (lane == 0) {
            float r0 = fmaxf(a0, 0.f) + EPS, r1 = fmaxf(a1, 0.f) + EPS;
            float r2 = fmaxf(a2, 0.f) + EPS, r3 = fmaxf(a3, 0.f) + EPS;
            if (task < 16) {
                float* d = &g_sel[(((b * HLEN + h) * RANK) + i) * RANK];
                d[0] = r0; d[1] = r1; d[2] = r2; d[3] = r3;
            } else if (task == 16) {
                g_alpha[b*4+0]=r0; g_alpha[b*4+1]=r1; g_alpha[b*4+2]=r2; g_alpha[b*4+3]=r3;
            } else {
                g_beta[b*4+0]=r0; g_beta[b*4+1]=r1; g_beta[b*4+2]=r2; g_beta[b*4+3]=r3;
            }
        }
    }
}

__global__ __launch_bounds__(256)
void finalize(float* __restrict__ out) {
    const int b = blockIdx.x, t = threadIdx.x;
    float v[4][4];
    #pragma unroll
    for (int i = 0; i < 4; i++) {
        float4 p = *(const float4*)&g_partial[(((size_t)b * 1024) + i * 256 + t) * 4];
        v[i][0] = p.x; v[i][1] = p.y; v[i][2] = p.z; v[i][3] = p.w;
    }
    #pragma unroll
    for (int off = 16; off > 0; off >>= 1)
        #pragma unroll
        for (int i = 0; i < 4; i++)
            #pragma unroll
            for (int j = 0; j < 4; j++)
                v[i][j] += __shfl_down_sync(0xffffffffu, v[i][j], off);
    __shared__ float ws[8][16];
    const int w = t >> 5, lane = t & 31;
    if (lane == 0)
        #pragma unroll
        for (int i = 0; i < 4; i++)
            #pragma unroll
            for (int j = 0; j < 4; j++) ws[w][i * 4 + j] = v[i][j];
    __syncthreads();
    if (t == 0) {
        float cm[4][4];
        #pragma unroll
        for (int i = 0; i < 4; i++)
            #pragma unroll
            for (int j = 0; j < 4; j++) {
                float s = (float)VOCAB * EPS;
                #pragma unroll
                for (int qq = 0; qq < 8; qq++) s += ws[qq][i * 4 + j];
                cm[i][j] = s;
            }
        float al[4], be[4];
        #pragma unroll
        for (int i = 0; i < 4; i++) { al[i] = g_alpha[b*4+i]; be[i] = g_beta[b*4+i]; }
        float m[4][4], tmp[4][4];
        const float* s0 = &g_sel[(b * HLEN + 0) * 16];
        #pragma unroll
        for (int i = 0; i < 4; i++)
            #pragma unroll
            for (int j = 0; j < 4; j++) m[i][j] = s0[i * 4 + j];
        for (int h = 1; h < HLEN; h++) {
            const float* sh = &g_sel[(b * HLEN + h) * 16];
            #pragma unroll
            for (int i = 0; i < 4; i++)
                #pragma unroll
                for (int j = 0; j < 4; j++) {
                    float a2 = 0.f;
                    #pragma unroll
                    for (int k = 0; k < 4; k++) a2 += m[i][k] * sh[k * 4 + j];
                    tmp[i][j] = a2;
                }
            #pragma unroll
            for (int i = 0; i < 4; i++)
                #pragma unroll
                for (int j = 0; j < 4; j++) m[i][j] = tmp[i][j];
        }
        float p_tilde = 0.f;
        #pragma unroll
        for (int i = 0; i < 4; i++)
            #pragma unroll
            for (int j = 0; j < 4; j++) p_tilde += al[i] * m[i][j] * be[j];
        float z[4][4];
        #pragma unroll
        for (int i = 0; i < 4; i++)
            #pragma unroll
            for (int j = 0; j < 4; j++) z[i][j] = cm[i][j];
        for (int r = 0; r < HLEN - 1; r++) {
            #pragma unroll
            for (int i = 0; i < 4; i++)
                #pragma unroll
                for (int j = 0; j < 4; j++) {
                    float a2 = 0.f;
                    #pragma unroll
                    for (int k = 0; k < 4; k++) a2 += z[i][k] * cm[k][j];
                    tmp[i][j] = a2;
                }
            #pragma unroll
            for (int i = 0; i < 4; i++)
                #pragma unroll
                for (int j = 0; j < 4; j++) z[i][j] = tmp[i][j];
        }
        float norm_const = 0.f;
        #pragma unroll
        for (int i = 0; i < 4; i++)
            #pragma unroll
            for (int j = 0; j < 4; j++) norm_const += al[i] * z[i][j] * be[j];
        out[b] = logf(norm_const) - logf(p_tilde);
    }
}

// =============================================================================
extern "C" void kernel_launch(void* const* d_in, const int* in_sizes, int n_in,
                              void* d_out, int out_size) {
    const float* x = nullptr; const float* wa = nullptr; const float* wb = nullptr;
    const float* wv = nullptr; const void* ix = nullptr;
    for (int i = 0; i < n_in; i++) {
        int s = in_sizes[i];
        if      (s == BATCH * EMB)   x  = (const float*)d_in[i];
        else if (s == 1024 * 262144) wv = (const float*)d_in[i];
        else if (s == BATCH * HLEN)  ix = d_in[i];
        else if (s == EMB * RANK)    { if (!wa) wa = (const float*)d_in[i];
                                       else     wb = (const float*)d_in[i]; }
    }
    if (!x || !wa || !wb || !wv || !ix) {
        x = (const float*)d_in[0]; wa = (const float*)d_in[1];
        wb = (const float*)d_in[2]; wv = (const float*)d_in[3]; ix = d_in[4];
    }
    float* out = (float*)d_out;

    normalize_indices<<<1, 256>>>(ix);
    gemm_mma<<<dim3(1024, 2), 256>>>(x, wv);
    small_dots<<<BATCH, 256>>>(x, wa, wb, wv);
    finalize<<<BATCH, 256>>>(out);
}

// round 5
// speedup vs baseline: 2.8257x; 1.0541x over previous
#include <cuda_runtime.h>
#include <math.h>
#include <stdint.h>

#define EMB    2048
#define RANK   4
#define VOCAB  8192
#define HLEN   4
#define BATCH  256
#define NCOLS  (VOCAB * RANK * RANK)   // 131072
#define EPS    1e-10f

// ---------------- scratch (__device__ globals) -------------------------------
__device__ float g_partial[BATCH * 1024 * 4];          // [row][tile 1024][j]
__device__ float g_sel  [BATCH * HLEN * RANK * RANK];
__device__ float g_alpha[BATCH * RANK];
__device__ float g_beta [BATCH * RANK];
__device__ int   g_idx32[BATCH * HLEN];

__device__ __forceinline__ uint32_t smem_u32(const void* p) {
    uint32_t a;
    asm("{ .reg .u64 t; cvta.to.shared.u64 t, %1; cvt.u32.u64 %0, t; }"
        : "=r"(a) : "l"(p));
    return a;
}
__device__ __forceinline__ void cp_async16(uint32_t saddr, const void* gaddr) {
    asm volatile("cp.async.cg.shared.global [%0], [%1], 16;"
                 :: "r"(saddr), "l"(gaddr) : "memory");
}
__device__ __forceinline__ void cp_commit() {
    asm volatile("cp.async.commit_group;" ::: "memory");
}
template <int N>
__device__ __forceinline__ void cp_wait() {
    asm volatile("cp.async.wait_group %0;" :: "n"(N) : "memory");
}
__device__ __forceinline__ void mma_tf32(float c[4], const uint32_t a[4],
                                         const uint32_t b[2]) {
    asm volatile(
        "mma.sync.aligned.m16n8k8.row.col.f32.tf32.tf32.f32 "
        "{%0,%1,%2,%3}, {%4,%5,%6,%7}, {%8,%9}, {%0,%1,%2,%3};"
        : "+f"(c[0]), "+f"(c[1]), "+f"(c[2]), "+f"(c[3])
        : "r"(a[0]), "r"(a[1]), "r"(a[2]), "r"(a[3]), "r"(b[0]), "r"(b[1]));
}

// =============================================================================
// HMMA tf32 GEMM: one CTA = D[256 batch rows][128 W cols], fused relu +
// j-bucket (col&3) reduction into g_partial[row][bn][4].
// grid (1024), 256 threads = 8 warps arranged 4(m) x 2(n), warp tile 64x64.
// =============================================================================
#define AP 20     // A smem row pitch (floats): conflict-free, 16B-aligned (80B)
#define BP 136    // B smem row pitch (floats): bank = 8q+g conflict-free, 544B
#define OFF_B   (2 * 256 * AP * 4)                 // 40960
#define SMEM_SZ (OFF_B + 2 * 16 * BP * 4)          // 40960 + 17408 = 58368

__global__ __launch_bounds__(256, 1)
void gemm_mma(const float* __restrict__ x, const float* __restrict__ w) {
    extern __shared__ float sm[];
    float* As = sm;                          // [2][256*AP]
    float* Bs = sm + OFF_B / 4;              // [2][16*BP]
    float (*red)[256][4] = (float (*)[256][4])sm;   // aliases As after mainloop

    const int t    = threadIdx.x;
    const int lane = t & 31;
    const int wid  = t >> 5;
    const int wy   = wid >> 1;          // 0..3  (m group of 64)
    const int wx   = wid & 1;           // 0..1  (n group of 64)
    const int bn   = blockIdx.x;        // 0..1023
    const int q    = lane & 3;
    const int g    = lane >> 2;

    float acc[4][8][4];
    #pragma unroll
    for (int mf = 0; mf < 4; mf++)
        #pragma unroll
        for (int nf = 0; nf < 8; nf++)
            #pragma unroll
            for (int r = 0; r < 4; r++) acc[mf][nf][r] = 0.f;

    const float* wg = w + (size_t)bn * 128;

    // --- stage issue: A = x[256 x 16], B = w[16 x 128] -----------------------
    auto issue = [&](int c, int s) {
        float* Ad = As + s * 256 * AP;
        #pragma unroll
        for (int i = 0; i < 4; i++) {
            int id  = t + 256 * i;              // 0..1023
            int row = id >> 2;                  // 0..255
            int seg = id & 3;                   // 16B segment
            cp_async16(smem_u32(Ad + row * AP + seg * 4),
                       x + (size_t)row * EMB + c * 16 + seg * 4);
        }
        float* Bd = Bs + s * 16 * BP;
        #pragma unroll
        for (int i = 0; i < 2; i++) {
            int id  = t + 256 * i;              // 0..511
            int kr  = id >> 5;                  // 0..15
            int seg = id & 31;
            cp_async16(smem_u32(Bd + kr * BP + seg * 4),
                       wg + (size_t)(c * 16 + kr) * NCOLS + seg * 4);
        }
        cp_commit();
    };

    issue(0, 0);
    const int NIT = EMB / 16;   // 128

    for (int c = 0; c < NIT; c++) {
        const int s = c & 1;
        if (c + 1 < NIT) { issue(c + 1, s ^ 1); cp_wait<1>(); }
        else             { cp_wait<0>(); }
        __syncthreads();

        const float* Aa = As + s * 256 * AP;
        const float* Bb = Bs + s * 16 * BP;

        #pragma unroll
        for (int k0 = 0; k0 < 16; k0 += 8) {
            uint32_t a[4][4];
            #pragma unroll
            for (int mf = 0; mf < 4; mf++) {
                int row = wy * 64 + mf * 16 + g;
                a[mf][0] = __float_as_uint(Aa[ row      * AP + k0 + q    ]);
                a[mf][1] = __float_as_uint(Aa[(row + 8) * AP + k0 + q    ]);
                a[mf][2] = __float_as_uint(Aa[ row      * AP + k0 + q + 4]);
                a[mf][3] = __float_as_uint(Aa[(row + 8) * AP + k0 + q + 4]);
            }
            #pragma unroll
            for (int nf = 0; nf < 8; nf++) {
                uint32_t b[2];
                int n = wx * 64 + nf * 8 + g;
                b[0] = __float_as_uint(Bb[(k0 + q)     * BP + n]);
                b[1] = __float_as_uint(Bb[(k0 + q + 4) * BP + n]);
                #pragma unroll
                for (int mf = 0; mf < 4; mf++)
                    mma_tf32(acc[mf][nf], a[mf], b);
            }
        }
        __syncthreads();
    }

    // --- epilogue: relu + j-bucket reduce ------------------------------------
    // c0/c1 at row g (cols 2q, 2q+1), c2/c3 at row g+8; j = (2q + reg) & 3.
    float sj[4][2][2];
    #pragma unroll
    for (int mf = 0; mf < 4; mf++) {
        sj[mf][0][0] = sj[mf][0][1] = sj[mf][1][0] = sj[mf][1][1] = 0.f;
        #pragma unroll
        for (int nf = 0; nf < 8; nf++) {
            sj[mf][0][0] += fmaxf(acc[mf][nf][0], 0.f);
            sj[mf][0][1] += fmaxf(acc[mf][nf][1], 0.f);
            sj[mf][1][0] += fmaxf(acc[mf][nf][2], 0.f);
            sj[mf][1][1] += fmaxf(acc[mf][nf][3], 0.f);
        }
        #pragma unroll
        for (int hh = 0; hh < 2; hh++)
            #pragma unroll
            for (int r = 0; r < 2; r++)
                sj[mf][hh][r] += __shfl_xor_sync(0xffffffffu, sj[mf][hh][r], 2);
    }
    if ((q >> 1) == 0) {               // q == 0,1 write; q == 2,3 hold dups
        const int jbase = (q & 1) ? 2 : 0;
        #pragma unroll
        for (int mf = 0; mf < 4; mf++)
            #pragma unroll
            for (int hh = 0; hh < 2; hh++) {
                int m = wy * 64 + mf * 16 + g + 8 * hh;
                red[wx][m][jbase + 0] = sj[mf][hh][0];
                red[wx][m][jbase + 1] = sj[mf][hh][1];
            }
    }
    __syncthreads();
    {
        float4 v;
        v.x = red[0][t][0] + red[1][t][0];
        v.y = red[0][t][1] + red[1][t][1];
        v.z = red[0][t][2] + red[1][t][2];
        v.w = red[0][t][3] + red[1][t][3];
        *(float4*)&g_partial[((size_t)t * 1024 + bn) * 4] = v;
    }
}

// =============================================================================
// indices normalize / small dots / finalize (unchanged, validated)
// =============================================================================
__global__ void normalize_indices(const void* __restrict__ idx_raw) {
    __shared__ int odd_nonzero;
    const int* w32 = (const int*)idx_raw;
    if (threadIdx.x == 0) odd_nonzero = 0;
    __syncthreads();
    for (int p = threadIdx.x; p < BATCH * HLEN; p += blockDim.x)
        if ((p & 1) && w32[p] != 0) atomicOr(&odd_nonzero, 1);
    __syncthreads();
    const bool is64 = (odd_nonzero == 0);
    const long long* w64 = (const long long*)idx_raw;
    for (int p = threadIdx.x; p < BATCH * HLEN; p += blockDim.x)
        g_idx32[p] = is64 ? (int)w64[p] : w32[p];
}

__global__ __launch_bounds__(256)
void small_dots(const float* __restrict__ x, const float* __restrict__ wa,
                const float* __restrict__ wb, const float* __restrict__ wv) {
    __shared__ float sx[EMB];
    const int b = blockIdx.x, t = threadIdx.x;
    for (int k = t; k < EMB; k += 256) sx[k] = x[(size_t)b * EMB + k];
    __syncthreads();
    const int w = t >> 5, lane = t & 31;
    for (int task = w; task < 18; task += 8) {
        const float* base; size_t stride; int h = 0, i = 0;
        if (task < 16) {
            h = task >> 2; i = task & 3;
            int v = g_idx32[b * HLEN + h];
            base = wv + (size_t)i * (VOCAB * RANK) + (size_t)v * RANK;
            stride = NCOLS;
        } else { base = (task == 16) ? wa : wb; stride = RANK; }
        float a0 = 0.f, a1 = 0.f, a2 = 0.f, a3 = 0.f;
        for (int k = lane; k < EMB; k += 32) {
            float xv = sx[k];
            float4 w4 = *(const float4*)(base + (size_t)k * stride);
            a0 += xv * w4.x; a1 += xv * w4.y; a2 += xv * w4.z; a3 += xv * w4.w;
        }
        #pragma unroll
        for (int off = 16; off > 0; off >>= 1) {
            a0 += __shfl_down_sync(0xffffffffu, a0, off);
            a1 += __shfl_down_sync(0xffffffffu, a1, off);
            a2 += __shfl_down_sync(0xffffffffu, a2, off);
            a3 += __shfl_down_sync(0xffffffffu, a3, off);
        }
        if (lane == 0) {
            float r0 = fmaxf(a0, 0.f) + EPS, r1 = fmaxf(a1, 0.f) + EPS;
            float r2 = fmaxf(a2, 0.f) + EPS, r3 = fmaxf(a3, 0.f) + EPS;
            if (task < 16) {
                float* d = &g_sel[(((b * HLEN + h) * RANK) + i) * RANK];
                d[0] = r0; d[1] = r1; d[2] = r2; d[3] = r3;
            } else if (task == 16) {
                g_alpha[b*4+0]=r0; g_alpha[b*4+1]=r1; g_alpha[b*4+2]=r2; g_alpha[b*4+3]=r3;
            } else {
                g_beta[b*4+0]=r0; g_beta[b*4+1]=r1; g_beta[b*4+2]=r2; g_beta[b*4+3]=r3;
            }
        }
    }
}

__global__ __launch_bounds__(256)
void finalize(float* __restrict__ out) {
    const int b = blockIdx.x, t = threadIdx.x;
    float v[4][4];
    #pragma unroll
    for (int i = 0; i < 4; i++) {
        float4 p = *(const float4*)&g_partial[(((size_t)b * 1024) + i * 256 + t) * 4];
        v[i][0] = p.x; v[i][1] = p.y; v[i][2] = p.z; v[i][3] = p.w;
    }
    #pragma unroll
    for (int off = 16; off > 0; off >>= 1)
        #pragma unroll
        for (int i = 0; i < 4; i++)
            #pragma unroll
            for (int j = 0; j < 4; j++)
                v[i][j] += __shfl_down_sync(0xffffffffu, v[i][j], off);
    __shared__ float ws[8][16];
    const int w = t >> 5, lane = t & 31;
    if (lane == 0)
        #pragma unroll
        for (int i = 0; i < 4; i++)
            #pragma unroll
            for (int j = 0; j < 4; j++) ws[w][i * 4 + j] = v[i][j];
    __syncthreads();
    if (t == 0) {
        float cm[4][4];
        #pragma unroll
        for (int i = 0; i < 4; i++)
            #pragma unroll
            for (int j = 0; j < 4; j++) {
                float s = (float)VOCAB * EPS;
                #pragma unroll
                for (int qq = 0; qq < 8; qq++) s += ws[qq][i * 4 + j];
                cm[i][j] = s;
            }
        float al[4], be[4];
        #pragma unroll
        for (int i = 0; i < 4; i++) { al[i] = g_alpha[b*4+i]; be[i] = g_beta[b*4+i]; }
        float m[4][4], tmp[4][4];
        const float* s0 = &g_sel[(b * HLEN + 0) * 16];
        #pragma unroll
        for (int i = 0; i < 4; i++)
            #pragma unroll
            for (int j = 0; j < 4; j++) m[i][j] = s0[i * 4 + j];
        for (int h = 1; h < HLEN; h++) {
            const float* sh = &g_sel[(b * HLEN + h) * 16];
            #pragma unroll
            for (int i = 0; i < 4; i++)
                #pragma unroll
                for (int j = 0; j < 4; j++) {
                    float a2 = 0.f;
                    #pragma unroll
                    for (int k = 0; k < 4; k++) a2 += m[i][k] * sh[k * 4 + j];
                    tmp[i][j] = a2;
                }
            #pragma unroll
            for (int i = 0; i < 4; i++)
                #pragma unroll
                for (int j = 0; j < 4; j++) m[i][j] = tmp[i][j];
        }
        float p_tilde = 0.f;
        #pragma unroll
        for (int i = 0; i < 4; i++)
            #pragma unroll
            for (int j = 0; j < 4; j++) p_tilde += al[i] * m[i][j] * be[j];
        float z[4][4];
        #pragma unroll
        for (int i = 0; i < 4; i++)
            #pragma unroll
            for (int j = 0; j < 4; j++) z[i][j] = cm[i][j];
        for (int r = 0; r < HLEN - 1; r++) {
            #pragma unroll
            for (int i = 0; i < 4; i++)
                #pragma unroll
                for (int j = 0; j < 4; j++) {
                    float a2 = 0.f;
                    #pragma unroll
                    for (int k = 0; k < 4; k++) a2 += z[i][k] * cm[k][j];
                    tmp[i][j] = a2;
                }
            #pragma unroll
            for (int i = 0; i < 4; i++)
                #pragma unroll
                for (int j = 0; j < 4; j++) z[i][j] = tmp[i][j];
        }
        float norm_const = 0.f;
        #pragma unroll
        for (int i = 0; i < 4; i++)
            #pragma unroll
            for (int j = 0; j < 4; j++) norm_const += al[i] * z[i][j] * be[j];
        out[b] = logf(norm_const) - logf(p_tilde);
    }
}

// =============================================================================
extern "C" void kernel_launch(void* const* d_in, const int* in_sizes, int n_in,
                              void* d_out, int out_size) {
    const float* x = nullptr; const float* wa = nullptr; const float* wb = nullptr;
    const float* wv = nullptr; const void* ix = nullptr;
    for (int i = 0; i < n_in; i++) {
        int s = in_sizes[i];
        if      (s == BATCH * EMB)   x  = (const float*)d_in[i];
        else if (s == 1024 * 262144) wv = (const float*)d_in[i];
        else if (s == BATCH * HLEN)  ix = d_in[i];
        else if (s == EMB * RANK)    { if (!wa) wa = (const float*)d_in[i];
                                       else     wb = (const float*)d_in[i]; }
    }
    if (!x || !wa || !wb || !wv || !ix) {
        x = (const float*)d_in[0]; wa = (const float*)d_in[1];
        wb = (const float*)d_in[2]; wv = (const float*)d_in[3]; ix = d_in[4];
    }
    float* out = (float*)d_out;

    static bool attr_set = false;
    if (!attr_set) {
        cudaFuncSetAttribute(gemm_mma, cudaFuncAttributeMaxDynamicSharedMemorySize,
                             SMEM_SZ);
        attr_set = true;
    }

    normalize_indices<<<1, 256>>>(ix);
    gemm_mma<<<1024, 256, SMEM_SZ>>>(x, wv);
    small_dots<<<BATCH, 256>>>(x, wa, wb, wv);
    finalize<<<BATCH, 256>>>(out);
}

// round 6
// speedup vs baseline: 4.3686x; 1.5460x over previous
#include <cuda_runtime.h>
#include <cuda_fp16.h>
#include <math.h>
#include <stdint.h>

#define EMB    2048
#define RANK   4
#define VOCAB  8192
#define HLEN   4
#define BATCH  256
#define NCOLS  (VOCAB * RANK * RANK)   // 131072
#define EPS    1e-10f

// ---------------- scratch (__device__ globals) -------------------------------
__device__ float g_partial[BATCH * 1024 * 4];          // [row][tile 1024][j]
__device__ float g_sel  [BATCH * HLEN * RANK * RANK];
__device__ float g_alpha[BATCH * RANK];
__device__ float g_beta [BATCH * RANK];
__device__ int   g_idx32[BATCH * HLEN];

__device__ __forceinline__ uint32_t smem_u32(const void* p) {
    uint32_t a;
    asm("{ .reg .u64 t; cvta.to.shared.u64 t, %1; cvt.u32.u64 %0, t; }"
        : "=r"(a) : "l"(p));
    return a;
}
__device__ __forceinline__ void mma_f16(float c[4], const uint32_t a[4],
                                        uint32_t b0, uint32_t b1) {
    asm volatile(
        "mma.sync.aligned.m16n8k16.row.col.f32.f16.f16.f32 "
        "{%0,%1,%2,%3}, {%4,%5,%6,%7}, {%8,%9}, {%0,%1,%2,%3};"
        : "+f"(c[0]), "+f"(c[1]), "+f"(c[2]), "+f"(c[3])
        : "r"(a[0]), "r"(a[1]), "r"(a[2]), "r"(a[3]), "r"(b0), "r"(b1));
}

// =============================================================================
// fp16 HMMA GEMM: one CTA = D[256 batch rows][128 W cols], fused relu +
// j-bucket (col&3) reduction into g_partial[row][bn][4].
// grid (1024), 256 threads = 8 warps (4 m x 2 n), warp tile 64x64, BK=32.
// fp32 -> fp16 conversion on the fly (LDG.128 -> cvt -> STS.64), reg double-buf.
// =============================================================================
#define AP_BYTES 80                      // A row pitch: 32 fp16 data + 8 pad
#define BP_BYTES 272                     // B row pitch: 128 fp16 data + 8 pad
#define A_STAGE  (256 * AP_BYTES)        // 20480
#define B_STAGE  (32 * BP_BYTES)         // 8704
#define OFF_BS   (2 * A_STAGE)           // 40960
#define SMEM_SZ  (OFF_BS + 2 * B_STAGE)  // 58368

__global__ __launch_bounds__(256, 1)
void gemm_mma(const float* __restrict__ x, const float* __restrict__ w) {
    extern __shared__ char sm[];
    const uint32_t sA = smem_u32(sm);
    const uint32_t sB = sA + OFF_BS;
    float (*red)[256][4] = (float (*)[256][4])sm;   // aliases A after mainloop

    const int t    = threadIdx.x;
    const int lane = t & 31;
    const int wid  = t >> 5;
    const int wy   = wid >> 1;          // 0..3  (m group of 64)
    const int wx   = wid & 1;           // 0..1  (n group of 64)
    const int bn   = blockIdx.x;        // 0..1023
    const int q    = lane & 3;
    const int g    = lane >> 2;
    const int jg   = lane >> 3;         // ldmatrix matrix group 0..3
    const int ig   = lane & 7;          // row within group

    // ldmatrix per-lane byte offsets (within a stage)
    const uint32_t aOff = (uint32_t)((wy * 64 + (jg & 1) * 8 + ig) * AP_BYTES
                                     + (jg >> 1) * 16);
    const uint32_t bOff = (uint32_t)(((jg & 1) * 8 + ig) * BP_BYTES
                                     + wx * 128 + (jg >> 1) * 16);

    float acc[4][8][4];
    #pragma unroll
    for (int mf = 0; mf < 4; mf++)
        #pragma unroll
        for (int nf = 0; nf < 8; nf++)
            #pragma unroll
            for (int r = 0; r < 4; r++) acc[mf][nf][r] = 0.f;

    const float* wg = w + (size_t)bn * 128;

    float4 aR[8], bR[4];   // register staging (double-buffer vs smem)

    auto ldg = [&](int c) {
        #pragma unroll
        for (int u = 0; u < 8; u++) {
            int id = t + 256 * u, row = id >> 3, seg = id & 7;
            aR[u] = *(const float4*)(x + (size_t)row * EMB + c * 32 + seg * 4);
        }
        #pragma unroll
        for (int u = 0; u < 4; u++) {
            int id = t + 256 * u, kr = id >> 5, seg = id & 31;
            bR[u] = *(const float4*)(wg + (size_t)(c * 32 + kr) * NCOLS + seg * 4);
        }
    };
    auto sts = [&](int s) {
        #pragma unroll
        for (int u = 0; u < 8; u++) {
            int id = t + 256 * u, row = id >> 3, seg = id & 7;
            __half2 h0 = __floats2half2_rn(aR[u].x, aR[u].y);
            __half2 h1 = __floats2half2_rn(aR[u].z, aR[u].w);
            uint2 v; v.x = *(uint32_t*)&h0; v.y = *(uint32_t*)&h1;
            *(uint2*)(sm + s * A_STAGE + row * AP_BYTES + seg * 8) = v;
        }
        #pragma unroll
        for (int u = 0; u < 4; u++) {
            int id = t + 256 * u, kr = id >> 5, seg = id & 31;
            __half2 h0 = __floats2half2_rn(bR[u].x, bR[u].y);
            __half2 h1 = __floats2half2_rn(bR[u].z, bR[u].w);
            uint2 v; v.x = *(uint32_t*)&h0; v.y = *(uint32_t*)&h1;
            *(uint2*)(sm + OFF_BS + s * B_STAGE + kr * BP_BYTES + seg * 8) = v;
        }
    };
    auto compute = [&](int s) {
        const uint32_t aBase = sA + s * A_STAGE + aOff;
        const uint32_t bBase = sB + s * B_STAGE + bOff;
        #pragma unroll
        for (int k16 = 0; k16 < 2; k16++) {
            uint32_t a[4][4];
            #pragma unroll
            for (int mf = 0; mf < 4; mf++) {
                uint32_t addr = aBase + mf * (16 * AP_BYTES) + k16 * 32;
                asm volatile(
                    "ldmatrix.sync.aligned.m8n8.x4.shared.b16 {%0,%1,%2,%3}, [%4];"
                    : "=r"(a[mf][0]), "=r"(a[mf][1]), "=r"(a[mf][2]), "=r"(a[mf][3])
                    : "r"(addr));
            }
            #pragma unroll
            for (int n16 = 0; n16 < 4; n16++) {
                uint32_t b[4];
                uint32_t addr = bBase + n16 * 32 + k16 * (16 * BP_BYTES);
                asm volatile(
                    "ldmatrix.sync.aligned.m8n8.x4.trans.shared.b16 {%0,%1,%2,%3}, [%4];"
                    : "=r"(b[0]), "=r"(b[1]), "=r"(b[2]), "=r"(b[3])
                    : "r"(addr));
                #pragma unroll
                for (int mf = 0; mf < 4; mf++) {
                    mma_f16(acc[mf][n16 * 2 + 0], a[mf], b[0], b[1]);
                    mma_f16(acc[mf][n16 * 2 + 1], a[mf], b[2], b[3]);
                }
            }
        }
    };

    // prologue
    ldg(0); sts(0); __syncthreads();

    const int NIT = EMB / 32;   // 64
    for (int c = 0; c < NIT; c++) {
        const int s = c & 1;
        if (c + 1 < NIT) ldg(c + 1);        // overlap DRAM with compute
        compute(s);
        if (c + 1 < NIT) {
            // all reads of stage s^1 finished before the sync at end of iter
            // c-1, so STS into s^1 here races nothing; one sync publishes it.
            sts(s ^ 1);
            __syncthreads();
        }
    }
    __syncthreads();   // protect `red` alias of A stages

    // --- epilogue: relu + j-bucket reduce (identical to validated R5) -------
    float sj[4][2][2];
    #pragma unroll
    for (int mf = 0; mf < 4; mf++) {
        sj[mf][0][0] = sj[mf][0][1] = sj[mf][1][0] = sj[mf][1][1] = 0.f;
        #pragma unroll
        for (int nf = 0; nf < 8; nf++) {
            sj[mf][0][0] += fmaxf(acc[mf][nf][0], 0.f);
            sj[mf][0][1] += fmaxf(acc[mf][nf][1], 0.f);
            sj[mf][1][0] += fmaxf(acc[mf][nf][2], 0.f);
            sj[mf][1][1] += fmaxf(acc[mf][nf][3], 0.f);
        }
        #pragma unroll
        for (int hh = 0; hh < 2; hh++)
            #pragma unroll
            for (int r = 0; r < 2; r++)
                sj[mf][hh][r] += __shfl_xor_sync(0xffffffffu, sj[mf][hh][r], 2);
    }
    if ((q >> 1) == 0) {               // q == 0,1 write; q == 2,3 hold dups
        const int jbase = (q & 1) ? 2 : 0;
        #pragma unroll
        for (int mf = 0; mf < 4; mf++)
            #pragma unroll
            for (int hh = 0; hh < 2; hh++) {
                int m = wy * 64 + mf * 16 + g + 8 * hh;
                red[wx][m][jbase + 0] = sj[mf][hh][0];
                red[wx][m][jbase + 1] = sj[mf][hh][1];
            }
    }
    __syncthreads();
    {
        float4 v;
        v.x = red[0][t][0] + red[1][t][0];
        v.y = red[0][t][1] + red[1][t][1];
        v.z = red[0][t][2] + red[1][t][2];
        v.w = red[0][t][3] + red[1][t][3];
        *(float4*)&g_partial[((size_t)t * 1024 + bn) * 4] = v;
    }
}

// =============================================================================
// indices normalize / small dots / finalize (unchanged, validated)
// =============================================================================
__global__ void normalize_indices(const void* __restrict__ idx_raw) {
    __shared__ int odd_nonzero;
    const int* w32 = (const int*)idx_raw;
    if (threadIdx.x == 0) odd_nonzero = 0;
    __syncthreads();
    for (int p = threadIdx.x; p < BATCH * HLEN; p += blockDim.x)
        if ((p & 1) && w32[p] != 0) atomicOr(&odd_nonzero, 1);
    __syncthreads();
    const bool is64 = (odd_nonzero == 0);
    const long long* w64 = (const long long*)idx_raw;
    for (int p = threadIdx.x; p < BATCH * HLEN; p += blockDim.x)
        g_idx32[p] = is64 ? (int)w64[p] : w32[p];
}

__global__ __launch_bounds__(256)
void small_dots(const float* __restrict__ x, const float* __restrict__ wa,
                const float* __restrict__ wb, const float* __restrict__ wv) {
    __shared__ float sx[EMB];
    const int b = blockIdx.x, t = threadIdx.x;
    for (int k = t; k < EMB; k += 256) sx[k] = x[(size_t)b * EMB + k];
    __syncthreads();
    const int w = t >> 5, lane = t & 31;
    for (int task = w; task < 18; task += 8) {
        const float* base; size_t stride; int h = 0, i = 0;
        if (task < 16) {
            h = task >> 2; i = task & 3;
            int v = g_idx32[b * HLEN + h];
            base = wv + (size_t)i * (VOCAB * RANK) + (size_t)v * RANK;
            stride = NCOLS;
        } else { base = (task == 16) ? wa : wb; stride = RANK; }
        float a0 = 0.f, a1 = 0.f, a2 = 0.f, a3 = 0.f;
        for (int k = lane; k < EMB; k += 32) {
            float xv = sx[k];
            float4 w4 = *(const float4*)(base + (size_t)k * stride);
            a0 += xv * w4.x; a1 += xv * w4.y; a2 += xv * w4.z; a3 += xv * w4.w;
        }
        #pragma unroll
        for (int off = 16; off > 0; off >>= 1) {
            a0 += __shfl_down_sync(0xffffffffu, a0, off);
            a1 += __shfl_down_sync(0xffffffffu, a1, off);
            a2 += __shfl_down_sync(0xffffffffu, a2, off);
            a3 += __shfl_down_sync(0xffffffffu, a3, off);
        }
        if (lane == 0) {
            float r0 = fmaxf(a0, 0.f) + EPS, r1 = fmaxf(a1, 0.f) + EPS;
            float r2 = fmaxf(a2, 0.f) + EPS, r3 = fmaxf(a3, 0.f) + EPS;
            if (task < 16) {
                float* d = &g_sel[(((b * HLEN + h) * RANK) + i) * RANK];
                d[0] = r0; d[1] = r1; d[2] = r2; d[3] = r3;
            } else if (task == 16) {
                g_alpha[b*4+0]=r0; g_alpha[b*4+1]=r1; g_alpha[b*4+2]=r2; g_alpha[b*4+3]=r3;
            } else {
                g_beta[b*4+0]=r0; g_beta[b*4+1]=r1; g_beta[b*4+2]=r2; g_beta[b*4+3]=r3;
            }
        }
    }
}

__global__ __launch_bounds__(256)
void finalize(float* __restrict__ out) {
    const int b = blockIdx.x, t = threadIdx.x;
    float v[4][4];
    #pragma unroll
    for (int i = 0; i < 4; i++) {
        float4 p = *(const float4*)&g_partial[(((size_t)b * 1024) + i * 256 + t) * 4];
        v[i][0] = p.x; v[i][1] = p.y; v[i][2] = p.z; v[i][3] = p.w;
    }
    #pragma unroll
    for (int off = 16; off > 0; off >>= 1)
        #pragma unroll
        for (int i = 0; i < 4; i++)
            #pragma unroll
            for (int j = 0; j < 4; j++)
                v[i][j] += __shfl_down_sync(0xffffffffu, v[i][j], off);
    __shared__ float ws[8][16];
    const int w = t >> 5, lane = t & 31;
    if (lane == 0)
        #pragma unroll
        for (int i = 0; i < 4; i++)
            #pragma unroll
            for (int j = 0; j < 4; j++) ws[w][i * 4 + j] = v[i][j];
    __syncthreads();
    if (t == 0) {
        float cm[4][4];
        #pragma unroll
        for (int i = 0; i < 4; i++)
            #pragma unroll
            for (int j = 0; j < 4; j++) {
                float s = (float)VOCAB * EPS;
                #pragma unroll
                for (int qq = 0; qq < 8; qq++) s += ws[qq][i * 4 + j];
                cm[i][j] = s;
            }
        float al[4], be[4];
        #pragma unroll
        for (int i = 0; i < 4; i++) { al[i] = g_alpha[b*4+i]; be[i] = g_beta[b*4+i]; }
        float m[4][4], tmp[4][4];
        const float* s0 = &g_sel[(b * HLEN + 0) * 16];
        #pragma unroll
        for (int i = 0; i < 4; i++)
            #pragma unroll
            for (int j = 0; j < 4; j++) m[i][j] = s0[i * 4 + j];
        for (int h = 1; h < HLEN; h++) {
            const float* sh = &g_sel[(b * HLEN + h) * 16];
            #pragma unroll
            for (int i = 0; i < 4; i++)
                #pragma unroll
                for (int j = 0; j < 4; j++) {
                    float a2 = 0.f;
                    #pragma unroll
                    for (int k = 0; k < 4; k++) a2 += m[i][k] * sh[k * 4 + j];
                    tmp[i][j] = a2;
                }
            #pragma unroll
            for (int i = 0; i < 4; i++)
                #pragma unroll
                for (int j = 0; j < 4; j++) m[i][j] = tmp[i][j];
        }
        float p_tilde = 0.f;
        #pragma unroll
        for (int i = 0; i < 4; i++)
            #pragma unroll
            for (int j = 0; j < 4; j++) p_tilde += al[i] * m[i][j] * be[j];
        float z[4][4];
        #pragma unroll
        for (int i = 0; i < 4; i++)
            #pragma unroll
            for (int j = 0; j < 4; j++) z[i][j] = cm[i][j];
        for (int r = 0; r < HLEN - 1; r++) {
            #pragma unroll
            for (int i = 0; i < 4; i++)
                #pragma unroll
                for (int j = 0; j < 4; j++) {
                    float a2 = 0.f;
                    #pragma unroll
                    for (int k = 0; k < 4; k++) a2 += z[i][k] * cm[k][j];
                    tmp[i][j] = a2;
                }
            #pragma unroll
            for (int i = 0; i < 4; i++)
                #pragma unroll
                for (int j = 0; j < 4; j++) z[i][j] = tmp[i][j];
        }
        float norm_const = 0.f;
        #pragma unroll
        for (int i = 0; i < 4; i++)
            #pragma unroll
            for (int j = 0; j < 4; j++) norm_const += al[i] * z[i][j] * be[j];
        out[b] = logf(norm_const) - logf(p_tilde);
    }
}

// =============================================================================
extern "C" void kernel_launch(void* const* d_in, const int* in_sizes, int n_in,
                              void* d_out, int out_size) {
    const float* x = nullptr; const float* wa = nullptr; const float* wb = nullptr;
    const float* wv = nullptr; const void* ix = nullptr;
    for (int i = 0; i < n_in; i++) {
        int s = in_sizes[i];
        if      (s == BATCH * EMB)   x  = (const float*)d_in[i];
        else if (s == 1024 * 262144) wv = (const float*)d_in[i];
        else if (s == BATCH * HLEN)  ix = d_in[i];
        else if (s == EMB * RANK)    { if (!wa) wa = (const float*)d_in[i];
                                       else     wb = (const float*)d_in[i]; }
    }
    if (!x || !wa || !wb || !wv || !ix) {
        x = (const float*)d_in[0]; wa = (const float*)d_in[1];
        wb = (const float*)d_in[2]; wv = (const float*)d_in[3]; ix = d_in[4];
    }
    float* out = (float*)d_out;

    static bool attr_set = false;
    if (!attr_set) {
        cudaFuncSetAttribute(gemm_mma, cudaFuncAttributeMaxDynamicSharedMemorySize,
                             SMEM_SZ);
        attr_set = true;
    }

    normalize_indices<<<1, 256>>>(ix);
    gemm_mma<<<1024, 256, SMEM_SZ>>>(x, wv);
    small_dots<<<BATCH, 256>>>(x, wa, wb, wv);
    finalize<<<BATCH, 256>>>(out);
}